// round 14
// baseline (speedup 1.0000x reference)
#include <cuda_runtime.h>

#define NN 50000
#define NE 1600000
#define HH 64
#define NG 16
#define DOUT 2

#define VPAD 68
#define NODES_B 64

// Scratch (device globals; zero-initialized at load; consumers tail-zero)
__device__ __align__(16) float g_relu_sum[NN * HH];
__device__ float g_deg[NN];
__device__ __align__(16) float g_pooled[NG * HH];
__device__ int g_done;

// ---------------------------------------------------------------------------
// Edge scatter, persistent: x lives in SMEM (200KB); 148 blocks x 1024 thr.
// 50000 chunks of 32 edges over 4736 warps. Random x reads -> random-bank LDS
// (~3-4 wavefronts) instead of ~30 L1 wavefronts.
#define EB_THREADS 1024
#define EB_WARPS (EB_THREADS / 32)
#define EB_GRID 148
__global__ void __launch_bounds__(EB_THREADS) edge_kernel(
    const float* __restrict__ x,
    const int* __restrict__ ei,
    const float* __restrict__ ea,
    const float* __restrict__ ew1,   // [5,64]
    const float* __restrict__ eb1)   // [64]
{
    extern __shared__ __align__(16) float esm[];
    float*  sx  = esm;                                   // NN floats
    float4* st4 = (float4*)(esm + NN);                   // EB_WARPS*32 float4
    float*  stx = (float*)(st4 + EB_WARPS * 32);         // EB_WARPS*32
    int*    stc = (int*)(stx + EB_WARPS * 32);           // EB_WARPS*32

    int tid = threadIdx.x;
    int warp = tid >> 5, lane = tid & 31;

    // Stage x into smem (coalesced float4)
    for (int i = tid; i < NN / 4; i += EB_THREADS)
        ((float4*)sx)[i] = ((const float4*)x)[i];
    // NN % 4 == 0 (50000/4 = 12500), no tail.

    int ja = lane, jb = lane + 32;
    float w0a = __ldg(&ew1[0 * 64 + ja]), w1a = __ldg(&ew1[1 * 64 + ja]);
    float w2a = __ldg(&ew1[2 * 64 + ja]), w3a = __ldg(&ew1[3 * 64 + ja]);
    float w4a = __ldg(&ew1[4 * 64 + ja]), ba  = __ldg(&eb1[ja]);
    float w0b = __ldg(&ew1[0 * 64 + jb]), w1b = __ldg(&ew1[1 * 64 + jb]);
    float w2b = __ldg(&ew1[2 * 64 + jb]), w3b = __ldg(&ew1[3 * 64 + jb]);
    float w4b = __ldg(&ew1[4 * 64 + jb]), bb  = __ldg(&eb1[jb]);

    __syncthreads();

    float4* my4 = &st4[warp * 32];
    float*  myx = &stx[warp * 32];
    int*    myc = &stc[warp * 32];

    const int NCHUNK = NE / 32;                          // 50000
    for (int chunk = blockIdx.x * EB_WARPS + warp; chunk < NCHUNK;
         chunk += EB_GRID * EB_WARPS) {
        int e = chunk * 32 + lane;

        int r = __ldg(&ei[e]);
        int c = __ldg(&ei[NE + e]);
        float xr = sx[r];                                // random-bank LDS
        float xc = sx[c];
        float a0 = __ldg(&ea[3 * e + 0]);
        float a1 = __ldg(&ea[3 * e + 1]);
        float a2 = __ldg(&ea[3 * e + 2]);
        atomicAdd(&g_deg[c], 1.0f);

        my4[lane] = make_float4(xr, a0, a1, a2);
        myx[lane] = xc;
        myc[lane] = c;
        __syncwarp();

#pragma unroll 8
        for (int k = 0; k < 32; k++) {
            float4 s  = my4[k];
            float xck = myx[k];
            int   ck  = myc[k];
            float h0 = fmaf(s.x, w0a, fmaf(xck, w1a,
                       fmaf(s.y, w2a, fmaf(s.z, w3a, fmaf(s.w, w4a, ba)))));
            float h1 = fmaf(s.x, w0b, fmaf(xck, w1b,
                       fmaf(s.y, w2b, fmaf(s.z, w3b, fmaf(s.w, w4b, bb)))));
            float* dst = &g_relu_sum[(size_t)ck * HH];
            atomicAdd(dst + ja, fmaxf(h0, 0.f));
            atomicAdd(dst + jb, fmaxf(h1, 0.f));
        }
        __syncwarp();
    }
}

// ---------------------------------------------------------------------------
// Column-parallel GEMV core: thread owns output col j (weights in REGISTERS),
// streams nodes; iv from broadcast LDS.128 (independent, pipelineable).
__device__ __forceinline__ float dot64(const float* __restrict__ row,
                                       const float* __restrict__ w, float acc) {
#pragma unroll
    for (int kq = 0; kq < 16; kq++) {
        float4 v = *(const float4*)&row[kq * 4];
        acc = fmaf(v.x, w[kq * 4 + 0], acc);
        acc = fmaf(v.y, w[kq * 4 + 1], acc);
        acc = fmaf(v.z, w[kq * 4 + 2], acc);
        acc = fmaf(v.w, w[kq * 4 + 3], acc);
    }
    return acc;
}

// ---------------------------------------------------------------------------
// Fused node pipeline + head MLP (last block). NODES_B=64 -> grid 782
// (5.3 blocks/SM available; reg-limited residency 3 -> full chip).
__global__ void __launch_bounds__(256, 3) node_out_kernel(
    const float* __restrict__ x,
    const int* __restrict__ batch,
    const float* __restrict__ ew2, const float* __restrict__ eb2,
    const float* __restrict__ nw1, const float* __restrict__ nb1,
    const float* __restrict__ nw2, const float* __restrict__ nb2,
    const float* __restrict__ ow1, const float* __restrict__ ob1,
    const float* __restrict__ ow2, const float* __restrict__ ob2,
    const float* __restrict__ ow3, const float* __restrict__ ob3,
    const float* __restrict__ ow4, const float* __restrict__ ob4,
    float* __restrict__ out)
{
    extern __shared__ __align__(16) float sm[];
    float* svecA = sm;                               // NODES_B*VPAD = 4352
    float* svecB = sm + NODES_B * VPAD;              // 4352
    float* sdg   = sm + 2 * NODES_B * VPAD;          // 64
    float* sxn   = sdg + NODES_B;                    // 64
    int*   sgb   = (int*)(sxn + NODES_B);            // 64
    float* spool = sxn + 2 * NODES_B;                // 1024

    int tid = threadIdx.x;
    int base = blockIdx.x * NODES_B;
    int nblk = min(NODES_B, NN - base);

    for (int i = tid; i < NG * HH; i += 256) spool[i] = 0.f;

    float4* gin = (float4*)g_relu_sum + (size_t)base * 16;
    const float4 z4 = make_float4(0.f, 0.f, 0.f, 0.f);
    for (int i = tid; i < nblk * 16; i += 256) {
        int nn = i >> 4, kv = i & 15;
        *(float4*)&svecA[nn * VPAD + kv * 4] = gin[i];
        gin[i] = z4;
    }
    if (tid < nblk) {
        int n = base + tid;
        sdg[tid] = g_deg[n];
        g_deg[n] = 0.f;
        sxn[tid] = __ldg(&x[n]);
        sgb[tid] = batch[n];
    }
    __syncthreads();

    int j = tid & 63;
    int mslot = tid >> 6;                            // 0..3, streams 16 nodes

    float w[64];

    // Phase A: B = deg*eb2 + A @ ew2
    {
        float bj = __ldg(&eb2[j]);
#pragma unroll
        for (int k = 0; k < 64; k++) w[k] = __ldg(&ew2[k * 64 + j]);
#pragma unroll 2
        for (int i = 0; i < NODES_B / 4; i++) {
            int n = mslot + i * 4;
            if (n < nblk) {
                float acc = dot64(&svecA[n * VPAD], w, sdg[n] * bj);
                svecB[n * VPAD + j] = acc;
            }
        }
    }
    __syncthreads();

    // Phase B: A = relu(nb1 + x*nw1[0] + B @ nw1[1:])
    {
        float bj  = __ldg(&nb1[j]);
        float w0j = __ldg(&nw1[j]);
#pragma unroll
        for (int k = 0; k < 64; k++) w[k] = __ldg(&nw1[(k + 1) * 64 + j]);
#pragma unroll 2
        for (int i = 0; i < NODES_B / 4; i++) {
            int n = mslot + i * 4;
            if (n < nblk) {
                float acc = dot64(&svecB[n * VPAD], w, fmaf(sxn[n], w0j, bj));
                svecA[n * VPAD + j] = fmaxf(acc, 0.f);
            }
        }
    }
    __syncthreads();

    // Phase C: h = nb2 + A @ nw2; pool
    {
        float bj = __ldg(&nb2[j]);
#pragma unroll
        for (int k = 0; k < 64; k++) w[k] = __ldg(&nw2[k * 64 + j]);
#pragma unroll 2
        for (int i = 0; i < NODES_B / 4; i++) {
            int n = mslot + i * 4;
            if (n < nblk) {
                float acc = dot64(&svecA[n * VPAD], w, bj);
                atomicAdd(&spool[sgb[n] * HH + j], acc);
            }
        }
    }
    __syncthreads();
    for (int i = tid; i < NG * HH; i += 256)
        atomicAdd(&g_pooled[i], spool[i]);

    // ---- last-block: head MLP ----
    __shared__ int s_last;
    __syncthreads();
    if (tid == 0) {
        __threadfence();
        int done = atomicAdd(&g_done, 1);
        s_last = (done == (int)gridDim.x - 1) ? 1 : 0;
    }
    __syncthreads();
    if (!s_last) return;
    __threadfence();

    float* sa   = spool;
    float* sbuf = svecA;                             // 4352 floats >= 1024
    for (int i = tid; i < NG * HH; i += 256) {
        sa[i] = __ldcg(&g_pooled[i]);
        g_pooled[i] = 0.f;
    }
    if (tid == 0) g_done = 0;
    __syncthreads();

#pragma unroll
    for (int it = 0; it < 4; it++) {
        int item = tid + it * 256;
        int gg = item >> 6, jj = item & 63;
        float v = __ldg(&ob1[jj]);
#pragma unroll 16
        for (int k = 0; k < 64; k++) v = fmaf(sa[gg * 64 + k], __ldg(&ow1[k * 64 + jj]), v);
        sbuf[item] = fmaxf(v, 0.f);
    }
    __syncthreads();
#pragma unroll
    for (int it = 0; it < 4; it++) {
        int item = tid + it * 256;
        int gg = item >> 6, jj = item & 63;
        float v = __ldg(&ob2[jj]);
#pragma unroll 16
        for (int k = 0; k < 64; k++) v = fmaf(sbuf[gg * 64 + k], __ldg(&ow2[k * 64 + jj]), v);
        sa[item] = fmaxf(v, 0.f);
    }
    __syncthreads();
#pragma unroll
    for (int it = 0; it < 4; it++) {
        int item = tid + it * 256;
        int gg = item >> 6, jj = item & 63;
        float v = __ldg(&ob3[jj]);
#pragma unroll 16
        for (int k = 0; k < 64; k++) v = fmaf(sa[gg * 64 + k], __ldg(&ow3[k * 64 + jj]), v);
        sbuf[item] = fmaxf(v, 0.f);
    }
    __syncthreads();
    if (tid < NG * DOUT) {
        int gg = tid / DOUT, jj = tid % DOUT;
        float o = __ldg(&ob4[jj]);
#pragma unroll 16
        for (int k = 0; k < 64; k++)
            o = fmaf(sbuf[gg * 64 + k], __ldg(&ow4[k * DOUT + jj]), o);
        out[gg * DOUT + jj] = o;
    }
}

// ---------------------------------------------------------------------------
extern "C" void kernel_launch(void* const* d_in, const int* in_sizes, int n_in,
                              void* d_out, int out_size) {
    const float* x     = (const float*)d_in[0];
    const int* ei      = (const int*)d_in[1];
    const float* ea    = (const float*)d_in[2];
    const int* batch   = (const int*)d_in[3];
    const float* ew1 = (const float*)d_in[4];
    const float* eb1 = (const float*)d_in[5];
    const float* ew2 = (const float*)d_in[6];
    const float* eb2 = (const float*)d_in[7];
    const float* nw1 = (const float*)d_in[8];
    const float* nb1 = (const float*)d_in[9];
    const float* nw2 = (const float*)d_in[10];
    const float* nb2 = (const float*)d_in[11];
    const float* ow1 = (const float*)d_in[12];
    const float* ob1 = (const float*)d_in[13];
    const float* ow2 = (const float*)d_in[14];
    const float* ob2 = (const float*)d_in[15];
    const float* ow3 = (const float*)d_in[16];
    const float* ob3 = (const float*)d_in[17];
    const float* ow4 = (const float*)d_in[18];
    const float* ob4 = (const float*)d_in[19];
    float* out = (float*)d_out;

    // edge smem: x (NN) + st4 (W*32*4) + stx (W*32) + stc (W*32)
    const int edge_smem = (NN + EB_WARPS * 32 * 6) * 4;              // 224768 B
    // node smem: svecA+svecB + sdg+sxn+sgb + spool
    const int node_smem = (2 * NODES_B * VPAD + 3 * NODES_B + NG * HH) * 4; // 39680 B
    static int smem_set = 0;
    if (!smem_set) {
        cudaFuncSetAttribute(edge_kernel,
                             cudaFuncAttributeMaxDynamicSharedMemorySize, edge_smem);
        cudaFuncSetAttribute(node_out_kernel,
                             cudaFuncAttributeMaxDynamicSharedMemorySize, node_smem);
        smem_set = 1;
    }

    edge_kernel<<<EB_GRID, EB_THREADS, edge_smem>>>(x, ei, ea, ew1, eb1);  // 1
    node_out_kernel<<<(NN + NODES_B - 1) / NODES_B, 256, node_smem>>>(     // 2
        x, batch, ew2, eb2, nw1, nb1, nw2, nb2,
        ow1, ob1, ow2, ob2, ow3, ob3, ow4, ob4, out);
}

// round 15
// speedup vs baseline: 1.0531x; 1.0531x over previous
#include <cuda_runtime.h>

#define NN 50000
#define NE 1600000
#define HH 64
#define NG 16
#define DOUT 2

#define VPAD 68
#define NODES_B 128

// Scratch (device globals; zero-initialized at load; consumers tail-zero)
__device__ __align__(16) float g_relu_sum[NN * HH];
__device__ float g_deg[NN];
__device__ __align__(16) float g_pooled[NG * HH];
__device__ int g_done;

// ---------------------------------------------------------------------------
// Edge scatter (R13 config): warp processes 32 edges; coalesced RED.32 x2.
__global__ void __launch_bounds__(256) edge_kernel(
    const float* __restrict__ x,
    const int* __restrict__ ei,
    const float* __restrict__ ea,
    const float* __restrict__ ew1,   // [5,64]
    const float* __restrict__ eb1)   // [64]
{
    __shared__ __align__(16) float4 st4[8][32];
    __shared__ float stx[8][32];
    __shared__ int   stc[8][32];

    int warp = threadIdx.x >> 5, lane = threadIdx.x & 31;
    int e = (blockIdx.x * 8 + warp) * 32 + lane;   // NE % 256 == 0

    int ja = lane, jb = lane + 32;
    float w0a = __ldg(&ew1[0 * 64 + ja]), w1a = __ldg(&ew1[1 * 64 + ja]);
    float w2a = __ldg(&ew1[2 * 64 + ja]), w3a = __ldg(&ew1[3 * 64 + ja]);
    float w4a = __ldg(&ew1[4 * 64 + ja]), ba  = __ldg(&eb1[ja]);
    float w0b = __ldg(&ew1[0 * 64 + jb]), w1b = __ldg(&ew1[1 * 64 + jb]);
    float w2b = __ldg(&ew1[2 * 64 + jb]), w3b = __ldg(&ew1[3 * 64 + jb]);
    float w4b = __ldg(&ew1[4 * 64 + jb]), bb  = __ldg(&eb1[jb]);

    int r = __ldg(&ei[e]);
    int c = __ldg(&ei[NE + e]);
    float xr = __ldg(&x[r]);
    float xc = __ldg(&x[c]);
    float a0 = __ldg(&ea[3 * e + 0]);
    float a1 = __ldg(&ea[3 * e + 1]);
    float a2 = __ldg(&ea[3 * e + 2]);
    atomicAdd(&g_deg[c], 1.0f);

    st4[warp][lane] = make_float4(xr, a0, a1, a2);
    stx[warp][lane] = xc;
    stc[warp][lane] = c;
    __syncwarp();

#pragma unroll 8
    for (int k = 0; k < 32; k++) {
        float4 s  = st4[warp][k];
        float xck = stx[warp][k];
        int   ck  = stc[warp][k];
        float h0 = fmaf(s.x, w0a, fmaf(xck, w1a,
                   fmaf(s.y, w2a, fmaf(s.z, w3a, fmaf(s.w, w4a, ba)))));
        float h1 = fmaf(s.x, w0b, fmaf(xck, w1b,
                   fmaf(s.y, w2b, fmaf(s.z, w3b, fmaf(s.w, w4b, bb)))));
        float* dst = &g_relu_sum[(size_t)ck * HH];
        atomicAdd(dst + ja, fmaxf(h0, 0.f));
        atomicAdd(dst + jb, fmaxf(h1, 0.f));
    }
}

// ---------------------------------------------------------------------------
// Column-parallel GEMV core with 4 INDEPENDENT accumulator chains.
// Chain length 16 (was 64) -> latency-hideable with 4 warps/SMSP.
__device__ __forceinline__ float dot64(const float* __restrict__ row,
                                       const float* __restrict__ w, float acc) {
    float a0 = acc, a1 = 0.f, a2 = 0.f, a3 = 0.f;
#pragma unroll
    for (int kb = 0; kb < 4; kb++) {
        float4 v0 = *(const float4*)&row[(kb * 4 + 0) * 4];
        float4 v1 = *(const float4*)&row[(kb * 4 + 1) * 4];
        float4 v2 = *(const float4*)&row[(kb * 4 + 2) * 4];
        float4 v3 = *(const float4*)&row[(kb * 4 + 3) * 4];
        const float* w0 = &w[(kb * 4 + 0) * 4];
        const float* w1 = &w[(kb * 4 + 1) * 4];
        const float* w2 = &w[(kb * 4 + 2) * 4];
        const float* w3 = &w[(kb * 4 + 3) * 4];
        a0 = fmaf(v0.x, w0[0], a0); a1 = fmaf(v1.x, w1[0], a1);
        a2 = fmaf(v2.x, w2[0], a2); a3 = fmaf(v3.x, w3[0], a3);
        a0 = fmaf(v0.y, w0[1], a0); a1 = fmaf(v1.y, w1[1], a1);
        a2 = fmaf(v2.y, w2[1], a2); a3 = fmaf(v3.y, w3[1], a3);
        a0 = fmaf(v0.z, w0[2], a0); a1 = fmaf(v1.z, w1[2], a1);
        a2 = fmaf(v2.z, w2[2], a2); a3 = fmaf(v3.z, w3[2], a3);
        a0 = fmaf(v0.w, w0[3], a0); a1 = fmaf(v1.w, w1[3], a1);
        a2 = fmaf(v2.w, w2[3], a2); a3 = fmaf(v3.w, w3[3], a3);
    }
    return (a0 + a1) + (a2 + a3);
}

// ---------------------------------------------------------------------------
// Fused node pipeline + head MLP (last block). R13 config: NODES_B=128.
// 256 threads: j = tid&63 (output column, weights in regs), mslot = tid>>6.
__global__ void __launch_bounds__(256, 3) node_out_kernel(
    const float* __restrict__ x,
    const int* __restrict__ batch,
    const float* __restrict__ ew2, const float* __restrict__ eb2,
    const float* __restrict__ nw1, const float* __restrict__ nb1,
    const float* __restrict__ nw2, const float* __restrict__ nb2,
    const float* __restrict__ ow1, const float* __restrict__ ob1,
    const float* __restrict__ ow2, const float* __restrict__ ob2,
    const float* __restrict__ ow3, const float* __restrict__ ob3,
    const float* __restrict__ ow4, const float* __restrict__ ob4,
    float* __restrict__ out)
{
    extern __shared__ __align__(16) float sm[];
    float* svecA = sm;                               // NODES_B*VPAD = 8704
    float* svecB = sm + NODES_B * VPAD;              // 8704
    float* sdg   = sm + 2 * NODES_B * VPAD;          // 128
    float* sxn   = sdg + NODES_B;                    // 128
    int*   sgb   = (int*)(sxn + NODES_B);            // 128
    float* spool = sxn + 2 * NODES_B;                // 1024

    int tid = threadIdx.x;
    int base = blockIdx.x * NODES_B;
    int nblk = min(NODES_B, NN - base);

    for (int i = tid; i < NG * HH; i += 256) spool[i] = 0.f;

    float4* gin = (float4*)g_relu_sum + (size_t)base * 16;
    const float4 z4 = make_float4(0.f, 0.f, 0.f, 0.f);
    for (int i = tid; i < nblk * 16; i += 256) {
        int nn = i >> 4, kv = i & 15;
        *(float4*)&svecA[nn * VPAD + kv * 4] = gin[i];
        gin[i] = z4;
    }
    if (tid < nblk) {
        int n = base + tid;
        sdg[tid] = g_deg[n];
        g_deg[n] = 0.f;
        sxn[tid] = __ldg(&x[n]);
        sgb[tid] = batch[n];
    }
    __syncthreads();

    int j = tid & 63;
    int mslot = tid >> 6;

    float w[64];

    // Phase A: B = deg*eb2 + A @ ew2
    {
        float bj = __ldg(&eb2[j]);
#pragma unroll
        for (int k = 0; k < 64; k++) w[k] = __ldg(&ew2[k * 64 + j]);
#pragma unroll 2
        for (int i = 0; i < NODES_B / 4; i++) {
            int n = mslot + i * 4;
            if (n < nblk) {
                float acc = dot64(&svecA[n * VPAD], w, sdg[n] * bj);
                svecB[n * VPAD + j] = acc;
            }
        }
    }
    __syncthreads();

    // Phase B: A = relu(nb1 + x*nw1[0] + B @ nw1[1:])
    {
        float bj  = __ldg(&nb1[j]);
        float w0j = __ldg(&nw1[j]);
#pragma unroll
        for (int k = 0; k < 64; k++) w[k] = __ldg(&nw1[(k + 1) * 64 + j]);
#pragma unroll 2
        for (int i = 0; i < NODES_B / 4; i++) {
            int n = mslot + i * 4;
            if (n < nblk) {
                float acc = dot64(&svecB[n * VPAD], w, fmaf(sxn[n], w0j, bj));
                svecA[n * VPAD + j] = fmaxf(acc, 0.f);
            }
        }
    }
    __syncthreads();

    // Phase C: h = nb2 + A @ nw2; pool
    {
        float bj = __ldg(&nb2[j]);
#pragma unroll
        for (int k = 0; k < 64; k++) w[k] = __ldg(&nw2[k * 64 + j]);
#pragma unroll 2
        for (int i = 0; i < NODES_B / 4; i++) {
            int n = mslot + i * 4;
            if (n < nblk) {
                float acc = dot64(&svecA[n * VPAD], w, bj);
                atomicAdd(&spool[sgb[n] * HH + j], acc);
            }
        }
    }
    __syncthreads();
    for (int i = tid; i < NG * HH; i += 256)
        atomicAdd(&g_pooled[i], spool[i]);

    // ---- last-block: head MLP ----
    __shared__ int s_last;
    __syncthreads();
    if (tid == 0) {
        __threadfence();
        int done = atomicAdd(&g_done, 1);
        s_last = (done == (int)gridDim.x - 1) ? 1 : 0;
    }
    __syncthreads();
    if (!s_last) return;
    __threadfence();

    float* sa   = spool;
    float* sbuf = svecA;
    for (int i = tid; i < NG * HH; i += 256) {
        sa[i] = __ldcg(&g_pooled[i]);
        g_pooled[i] = 0.f;
    }
    if (tid == 0) g_done = 0;
    __syncthreads();

#pragma unroll
    for (int it = 0; it < 4; it++) {
        int item = tid + it * 256;
        int gg = item >> 6, jj = item & 63;
        float v = __ldg(&ob1[jj]);
#pragma unroll 16
        for (int k = 0; k < 64; k++) v = fmaf(sa[gg * 64 + k], __ldg(&ow1[k * 64 + jj]), v);
        sbuf[item] = fmaxf(v, 0.f);
    }
    __syncthreads();
#pragma unroll
    for (int it = 0; it < 4; it++) {
        int item = tid + it * 256;
        int gg = item >> 6, jj = item & 63;
        float v = __ldg(&ob2[jj]);
#pragma unroll 16
        for (int k = 0; k < 64; k++) v = fmaf(sbuf[gg * 64 + k], __ldg(&ow2[k * 64 + jj]), v);
        sa[item] = fmaxf(v, 0.f);
    }
    __syncthreads();
#pragma unroll
    for (int it = 0; it < 4; it++) {
        int item = tid + it * 256;
        int gg = item >> 6, jj = item & 63;
        float v = __ldg(&ob3[jj]);
#pragma unroll 16
        for (int k = 0; k < 64; k++) v = fmaf(sa[gg * 64 + k], __ldg(&ow3[k * 64 + jj]), v);
        sbuf[item] = fmaxf(v, 0.f);
    }
    __syncthreads();
    if (tid < NG * DOUT) {
        int gg = tid / DOUT, jj = tid % DOUT;
        float o = __ldg(&ob4[jj]);
#pragma unroll 16
        for (int k = 0; k < 64; k++)
            o = fmaf(sbuf[gg * 64 + k], __ldg(&ow4[k * DOUT + jj]), o);
        out[gg * DOUT + jj] = o;
    }
}

// ---------------------------------------------------------------------------
extern "C" void kernel_launch(void* const* d_in, const int* in_sizes, int n_in,
                              void* d_out, int out_size) {
    const float* x     = (const float*)d_in[0];
    const int* ei      = (const int*)d_in[1];
    const float* ea    = (const float*)d_in[2];
    const int* batch   = (const int*)d_in[3];
    const float* ew1 = (const float*)d_in[4];
    const float* eb1 = (const float*)d_in[5];
    const float* ew2 = (const float*)d_in[6];
    const float* eb2 = (const float*)d_in[7];
    const float* nw1 = (const float*)d_in[8];
    const float* nb1 = (const float*)d_in[9];
    const float* nw2 = (const float*)d_in[10];
    const float* nb2 = (const float*)d_in[11];
    const float* ow1 = (const float*)d_in[12];
    const float* ob1 = (const float*)d_in[13];
    const float* ow2 = (const float*)d_in[14];
    const float* ob2 = (const float*)d_in[15];
    const float* ow3 = (const float*)d_in[16];
    const float* ob3 = (const float*)d_in[17];
    const float* ow4 = (const float*)d_in[18];
    const float* ob4 = (const float*)d_in[19];
    float* out = (float*)d_out;

    const int node_smem = (2 * NODES_B * VPAD + 3 * NODES_B + NG * HH) * 4;  // 75264 B
    static int smem_set = 0;
    if (!smem_set) {
        cudaFuncSetAttribute(node_out_kernel,
                             cudaFuncAttributeMaxDynamicSharedMemorySize, node_smem);
        smem_set = 1;
    }

    edge_kernel<<<NE / 256, 256>>>(x, ei, ea, ew1, eb1);               // 1
    node_out_kernel<<<(NN + NODES_B - 1) / NODES_B, 256, node_smem>>>( // 2
        x, batch, ew2, eb2, nw1, nb1, nw2, nb2,
        ow1, ob1, ow2, ob2, ow3, ob3, ow4, ob4, out);
}